// round 4
// baseline (speedup 1.0000x reference)
#include <cuda_runtime.h>
#include <math_constants.h>

#define NSEG 128
#define P    512
#define D    64
#define KT   15
#define NC   8
#define CPS  4            // CTAs per segment
#define TPB  256
#define PPC  (P / CPS)    // 128 points per CTA

__device__ float g_sdist[NSEG * P];      // per-point squared distances
__device__ float g_partials[NSEG];
__device__ int   g_seg_ticket[NSEG];     // zero-init; reset by finisher
__device__ int   g_ticket2 = 0;          // reset by last finisher

__global__ __launch_bounds__(TPB)
void lmnn_kernel(const float* __restrict__ center,
                 const float* __restrict__ outputs,
                 const int*   __restrict__ labels,
                 float*       __restrict__ out)
{
    __shared__ float4 scen[16];          // this segment's center (64 floats)
    __shared__ float  sdist[P];
    __shared__ int    slab[P];
    __shared__ float  sS[NC];
    __shared__ float  sM[NC];
    __shared__ int    sCnt[NC];
    __shared__ float  sred[TPB / 32];
    __shared__ int    s_go, s_final;

    const int bid     = blockIdx.x;
    const int seg     = bid >> 2;
    const int quarter = bid & 3;
    const int t       = threadIdx.x;
    const int w       = t >> 5;
    const int lane    = t & 31;
    const int q       = t >> 1;          // local point 0..127
    const int half    = t & 1;           // which 32-float half of the row

    // ---- Phase 1: squared distance for PPC points of this segment ----
    const float4* __restrict__ out4 = (const float4*)(outputs + (size_t)seg * P * D);
    if (t < 16) scen[t] = ((const float4*)(center + seg * D))[t];

    // Each lane owns one contiguous 128B half-row (8 float4s). Front-batch.
    const int base4 = (quarter * PPC + q) * 16 + half * 8;
    float4 v[8];
    #pragma unroll
    for (int u = 0; u < 8; ++u)
        v[u] = __ldcs(&out4[base4 + u]);
    __syncthreads();   // scen ready

    float a0 = 0.0f, a1 = 0.0f;
    #pragma unroll
    for (int u = 0; u < 8; ++u) {
        const float4 cc = scen[half * 8 + u];
        const float dx = v[u].x - cc.x;
        const float dy = v[u].y - cc.y;
        const float dz = v[u].z - cc.z;
        const float dw = v[u].w - cc.w;
        const float p4 = dx * dx + dy * dy + dz * dz + dw * dw;
        if (u & 1) a1 += p4; else a0 += p4;
    }
    float part = a0 + a1;
    part += __shfl_xor_sync(0xffffffffu, part, 1);   // combine the two halves
    if (half == 0)
        g_sdist[seg * P + quarter * PPC + q] = part;

    // ---- make writes visible, then vote on per-segment ticket ----
    __threadfence();
    __syncthreads();
    if (t == 0) {
        const int prev = atomicAdd(&g_seg_ticket[seg], 1);
        s_go = (prev == CPS - 1) ? 1 : 0;
    }
    __syncthreads();
    if (!s_go) return;                    // non-finisher CTAs are done
    __threadfence();                      // acquire other CTAs' scratch writes

    // ================== FINISHER: full-segment phases ==================
    slab[t]        = labels[seg * P + t];
    slab[t + 256]  = labels[seg * P + t + 256];
    sdist[t]       = g_sdist[seg * P + t];
    sdist[t + 256] = g_sdist[seg * P + t + 256];
    __syncthreads();

    // ---- Phase 2: per-class stats; warp w (8 warps total) = class w ----
    // top_k over -dd has all finite entries equal (dist broadcast along k),
    // so jax tie-breaking selects the FIRST KT same-class indices.
    {
        const int c = w;
        float S  = 0.0f;
        float Mx = -CUDART_INF_F;
        int   cnt = 0;
        int   taken = 0;
        #pragma unroll 4
        for (int base = 0; base < P; base += 32) {
            const bool m = (slab[base + lane] == c);
            const unsigned mask = __ballot_sync(0xffffffffu, m);
            const int pc = __popc(mask);
            const int need = KT - taken;
            if (need > 0) {
                const int rank = __popc(mask & ((1u << lane) - 1u));
                if (m && rank < need) {
                    const float dv = sdist[base + lane];
                    S += dv;
                    Mx = fmaxf(Mx, dv);
                }
                taken += (pc < need) ? pc : need;
            }
            cnt += pc;
        }
        #pragma unroll
        for (int off = 16; off > 0; off >>= 1) {
            S += __shfl_xor_sync(0xffffffffu, S, off);
            Mx = fmaxf(Mx, __shfl_xor_sync(0xffffffffu, Mx, off));
        }
        if (lane == 0) { sS[c] = S; sM[c] = Mx; sCnt[c] = cnt; }
    }
    __syncthreads();

    // ---- Phase 3: margin_seg = 1 + max over present classes ----
    float ms = -CUDART_INF_F;
    #pragma unroll
    for (int c = 0; c < NC; ++c)
        if (sCnt[c] > 0) ms = fmaxf(ms, sM[c]);
    ms += 1.0f;

    // ---- Phase 4: push term; each thread handles points t and t+256 ----
    float term = 0.0f;
    #pragma unroll
    for (int rep = 0; rep < 2; ++rep) {
        const int   j  = t + rep * 256;
        const int   cj = slab[j];
        const float dv = sdist[j];
        if (dv < ms)
            term += (float)(P - sCnt[cj]) * fmaxf(1.0f + sM[cj] - dv, 0.0f);
    }
    #pragma unroll
    for (int off = 16; off > 0; off >>= 1)
        term += __shfl_xor_sync(0xffffffffu, term, off);
    if (lane == 0) sred[w] = term;
    __syncthreads();

    // ---- Phase 5: per-segment total; last finisher reduces all ----
    if (t == 0) {
        float push = 0.0f;
        #pragma unroll
        for (int k = 0; k < TPB / 32; ++k) push += sred[k];
        float pull = 0.0f;
        #pragma unroll
        for (int c = 0; c < NC; ++c)
            pull += (float)sCnt[c] * sS[c];
        g_partials[seg] = pull + push;
        g_seg_ticket[seg] = 0;            // reset for next graph replay
        __threadfence();
        const int prev2 = atomicAdd(&g_ticket2, 1);
        s_final = (prev2 == NSEG - 1) ? 1 : 0;
    }
    __syncthreads();

    if (s_final && w == 0) {
        __threadfence();
        float a  = g_partials[lane];
        float b  = g_partials[lane + 32];
        float c2 = g_partials[lane + 64];
        float d2 = g_partials[lane + 96];
        float vsum = (a + b) + (c2 + d2);
        #pragma unroll
        for (int off = 16; off > 0; off >>= 1)
            vsum += __shfl_xor_sync(0xffffffffu, vsum, off);
        if (lane == 0) {
            out[0] = vsum * (1.0f / (float)(NSEG * P));
            g_ticket2 = 0;                // reset for next graph replay
        }
    }
}

extern "C" void kernel_launch(void* const* d_in, const int* in_sizes, int n_in,
                              void* d_out, int out_size)
{
    const float* center  = (const float*)d_in[0];  // (128, 64)    f32
    const float* outputs = (const float*)d_in[1];  // (128,512,64) f32
    const int*   labels  = (const int*)d_in[2];    // (128, 512)   i32

    lmnn_kernel<<<NSEG * CPS, TPB>>>(center, outputs, labels, (float*)d_out);
}

// round 5
// speedup vs baseline: 1.4048x; 1.4048x over previous
#include <cuda_runtime.h>
#include <math_constants.h>

#define NSEG 128
#define P    512
#define D    64
#define KT   15
#define NC   8
#define NT   1024
#define NW   (NT/32)

__device__ float g_partials[NSEG];
__device__ int   g_ticket = 0;   // reset by last block each launch

__global__ __launch_bounds__(NT, 1)
void lmnn_fused_kernel(const float* __restrict__ center,
                       const float* __restrict__ outputs,
                       const int*   __restrict__ labels,
                       float*       __restrict__ out)
{
    __shared__ float sdist[P];
    __shared__ int   slab[P];
    __shared__ short sidx[NC][16];   // first-KT member indices per class
    __shared__ int   sCnt[NC];
    __shared__ int   sTaken[NC];
    __shared__ float sS[NC];
    __shared__ float sM[NC];
    __shared__ float sred[NW];
    __shared__ int   s_last;

    const int seg  = blockIdx.x;
    const int t    = threadIdx.x;
    const int w    = t >> 5;
    const int lane = t & 31;

    // ---- Issue the big loads FIRST (front-batched, coalesced, streaming) ----
    // 8192 float4s/segment; thread t takes g = t + 1024*s. (t&15) = d-offset.
    const float4* __restrict__ out4 = (const float4*)(outputs + (size_t)seg * P * D);
    float4 v[8];
    #pragma unroll
    for (int s = 0; s < 8; ++s)
        v[s] = __ldcs(&out4[t + NT * s]);
    const float4 c4 = __ldg(&((const float4*)(center + seg * D))[t & 15]);

    // ---- Class scan (warps 0..7), hidden under the load latency above. ----
    // Labels loaded directly from global (2KB, independent of smem/barriers).
    // Key: top_k over -dd has all finite entries equal (dist broadcast along
    // k), so jax tie-breaking selects the FIRST KT same-class indices.
    if (w < NC) {
        int lab[16];
        #pragma unroll
        for (int u = 0; u < 16; ++u)
            lab[u] = __ldg(&labels[seg * P + u * 32 + lane]);
        // warp 0 also publishes labels to smem for the push phase
        if (w == 0) {
            #pragma unroll
            for (int u = 0; u < 16; ++u)
                slab[u * 32 + lane] = lab[u];
        }
        int cnt = 0, taken = 0;
        #pragma unroll
        for (int u = 0; u < 16; ++u) {
            const bool m = (lab[u] == w);
            const unsigned mask = __ballot_sync(0xffffffffu, m);
            const int pc = __popc(mask);
            const int need = KT - taken;
            if (need > 0) {
                const int rank = __popc(mask & ((1u << lane) - 1u));
                if (m && rank < need)
                    sidx[w][taken + rank] = (short)(u * 32 + lane);
                taken += (pc < need) ? pc : need;
            }
            cnt += pc;
        }
        if (lane == 0) { sCnt[w] = cnt; sTaken[w] = taken; }
    }

    // ---- Distance compute: 16 lanes = one point ----
    #pragma unroll
    for (int s = 0; s < 8; ++s) {
        const int g = t + NT * s;
        const float dx = v[s].x - c4.x;
        const float dy = v[s].y - c4.y;
        const float dz = v[s].z - c4.z;
        const float dw = v[s].w - c4.w;
        float part = dx * dx + dy * dy + dz * dz + dw * dw;
        part += __shfl_down_sync(0xffffffffu, part, 8);
        part += __shfl_down_sync(0xffffffffu, part, 4);
        part += __shfl_down_sync(0xffffffffu, part, 2);
        part += __shfl_down_sync(0xffffffffu, part, 1);
        if ((t & 15) == 0) sdist[g >> 4] = part;
    }
    __syncthreads();

    // ---- Gather: warp c<8, 15-element gather + shfl reduce (short path) ----
    if (w < NC) {
        const int cnt   = sCnt[w];
        const int taken = sTaken[w];
        float d = (lane < KT)
                    ? ((lane < taken) ? sdist[sidx[w][lane]] : CUDART_INF_F)
                    : 0.0f;
        float S  = (lane < KT) ? d : 0.0f;
        float Mx = (lane < KT) ? d : -CUDART_INF_F;
        #pragma unroll
        for (int off = 16; off > 0; off >>= 1) {
            S += __shfl_xor_sync(0xffffffffu, S, off);
            Mx = fmaxf(Mx, __shfl_xor_sync(0xffffffffu, Mx, off));
        }
        if (lane == 0) {
            sS[w] = (cnt > 0) ? S : 0.0f;            // avoid 0*inf
            sM[w] = (cnt > 0) ? Mx : -CUDART_INF_F;  // excluded from margin
        }
    }
    __syncthreads();

    // ---- margin_seg = 1 + max over present classes ----
    float ms = -CUDART_INF_F;
    #pragma unroll
    for (int c = 0; c < NC; ++c)
        ms = fmaxf(ms, sM[c]);
    ms += 1.0f;

    // ---- push term per point (first 512 threads) ----
    float term = 0.0f;
    if (t < P) {
        const int   cj = slab[t];
        const float dv = sdist[t];
        if (dv < ms)
            term = (float)(P - sCnt[cj]) * fmaxf(1.0f + sM[cj] - dv, 0.0f);
    }
    #pragma unroll
    for (int off = 16; off > 0; off >>= 1)
        term += __shfl_xor_sync(0xffffffffu, term, off);
    if (lane == 0) sred[w] = term;
    __syncthreads();

    // ---- per-segment partial + last-block finish ----
    if (t == 0) {
        float push = 0.0f;
        #pragma unroll
        for (int k = 0; k < NW; ++k) push += sred[k];
        float pull = 0.0f;
        #pragma unroll
        for (int c = 0; c < NC; ++c)
            pull += (float)sCnt[c] * sS[c];
        g_partials[seg] = pull + push;
        __threadfence();
        const int prev = atomicAdd(&g_ticket, 1);
        s_last = (prev == NSEG - 1) ? 1 : 0;
    }
    __syncthreads();

    if (s_last && w == 0) {
        __threadfence();
        const float a  = g_partials[lane];
        const float b  = g_partials[lane + 32];
        const float c2 = g_partials[lane + 64];
        const float d2 = g_partials[lane + 96];
        float vsum = (a + b) + (c2 + d2);
        #pragma unroll
        for (int off = 16; off > 0; off >>= 1)
            vsum += __shfl_xor_sync(0xffffffffu, vsum, off);
        if (lane == 0) {
            out[0] = vsum * (1.0f / (float)(NSEG * P));
            g_ticket = 0;   // reset for next graph replay
        }
    }
}

extern "C" void kernel_launch(void* const* d_in, const int* in_sizes, int n_in,
                              void* d_out, int out_size)
{
    const float* center  = (const float*)d_in[0];  // (128, 64)    f32
    const float* outputs = (const float*)d_in[1];  // (128,512,64) f32
    const int*   labels  = (const int*)d_in[2];    // (128, 512)   i32

    lmnn_fused_kernel<<<NSEG, NT>>>(center, outputs, labels, (float*)d_out);
}